// round 11
// baseline (speedup 1.0000x reference)
#include <cuda_runtime.h>
#include <cuda_fp16.h>
#include <cstdint>

// SmileMoENorm — TMA bulk-staged version: 32KB read bursts, 32KB write
// bursts per CTA to maximize HBM direction run-length (R6 vs R10 showed
// DRAM% tracks direction batching). 2048 CTAs x 64 tokens (8 stages of 8).
// smem: 3 in-buffers + 2 out-buffers (32KB each) + mbarriers. 1 CTA/SM.
// Epilogue math identical to R6 (packed-fp16 gamma/beta, k_pack + PDL).

#define N_TOKENS    131072
#define HIDDEN      1024
#define NUM_EXPERTS 8
#define H4          (HIDDEN / 4)
#define EPS         1e-5f

#define TOK_PER_STAGE 8
#define STAGE_BYTES   (TOK_PER_STAGE * HIDDEN * 4)   // 32768
#define N_STAGES      8                              // 64 tokens per CTA
#define GRID          (N_TOKENS / (TOK_PER_STAGE * N_STAGES))  // 2048

#define SMEM_IN_OFF   0
#define SMEM_OUT_OFF  (3 * STAGE_BYTES)              // 98304
#define SMEM_MBAR_OFF (5 * STAGE_BYTES)              // 163840
#define SMEM_TOTAL    (5 * STAGE_BYTES + 64)

__device__ __half2 d_pk[NUM_EXPERTS * HIDDEN];   // (gamma, beta) per element

// ---- pre-pass: pack gamma/beta into fp16 -----------------------------------
__global__ void k_pack(const float4* __restrict__ gamma4,
                       const float4* __restrict__ beta4) {
    cudaTriggerProgrammaticLaunchCompletion();
    const int i = blockIdx.x * blockDim.x + threadIdx.x;   // 0..2047
    const float4 g = gamma4[i];
    const float4 b = beta4[i];
    __half2* dst = d_pk + i * 4;
    dst[0] = __floats2half2_rn(g.x, b.x);
    dst[1] = __floats2half2_rn(g.y, b.y);
    dst[2] = __floats2half2_rn(g.z, b.z);
    dst[3] = __floats2half2_rn(g.w, b.w);
}

// ---- PTX helpers ------------------------------------------------------------
__device__ __forceinline__ uint32_t smem_u32(const void* p) {
    uint32_t a;
    asm("{ .reg .u64 t; cvta.to.shared.u64 t, %1; cvt.u32.u64 %0, t; }"
        : "=r"(a) : "l"(p));
    return a;
}
__device__ __forceinline__ void mbar_init(uint32_t mbar, uint32_t cnt) {
    asm volatile("mbarrier.init.shared.b64 [%0], %1;" :: "r"(mbar), "r"(cnt) : "memory");
}
__device__ __forceinline__ void mbar_expect_tx(uint32_t mbar, uint32_t bytes) {
    asm volatile("mbarrier.arrive.expect_tx.shared.b64 _, [%0], %1;"
                 :: "r"(mbar), "r"(bytes) : "memory");
}
__device__ __forceinline__ void mbar_wait(uint32_t mbar, uint32_t parity) {
    asm volatile("{\n\t.reg .pred P;\n"
                 "W:\n\tmbarrier.try_wait.parity.acquire.cta.shared::cta.b64 P, [%0], %1;\n"
                 "\t@P bra D;\n\tbra W;\nD:\n\t}"
                 :: "r"(mbar), "r"(parity) : "memory");
}
__device__ __forceinline__ void bulk_load(uint32_t smem, const void* gmem,
                                          uint32_t bytes, uint32_t mbar) {
    asm volatile("cp.async.bulk.shared::cluster.global.mbarrier::complete_tx::bytes "
                 "[%0], [%1], %2, [%3];"
                 :: "r"(smem), "l"(gmem), "r"(bytes), "r"(mbar) : "memory");
}
__device__ __forceinline__ void bulk_store(void* gmem, uint32_t smem, uint32_t bytes) {
    asm volatile("cp.async.bulk.global.shared::cta.bulk_group [%0], [%1], %2;"
                 :: "l"(gmem), "r"(smem), "r"(bytes) : "memory");
}

// ---- router: top-2 of 8 logits, renormalized softmax ------------------------
__device__ __forceinline__ void route8(float4 la, float4 lb,
                                       int& e0, int& e1,
                                       __half2& w0h, __half2& w1h) {
    float l[NUM_EXPERTS] = { la.x, la.y, la.z, la.w, lb.x, lb.y, lb.z, lb.w };
    float best = l[0], second = -3.4e38f;
    e0 = 0; e1 = 0;
    #pragma unroll
    for (int i = 1; i < NUM_EXPERTS; i++) {
        float v = l[i];
        if (v > best)        { second = best; e1 = e0; best = v; e0 = i; }
        else if (v > second) { second = v; e1 = i; }
    }
    const float w0 = 1.0f / (1.0f + __expf(second - best));
    w0h = __float2half2_rn(w0);
    w1h = __float2half2_rn(1.0f - w0);
}

// ------------------------------------------------------------- main kernel
__global__ __launch_bounds__(256, 1)
void smile_moe_norm_kernel(const float* __restrict__ x,
                           const float4* __restrict__ logits4,   // [N,2] float4
                           float* __restrict__ out) {
    extern __shared__ char smem[];
    const uint32_t smem_base = smem_u32(smem);
    const uint32_t in_base   = smem_base + SMEM_IN_OFF;
    const uint32_t out_base  = smem_base + SMEM_OUT_OFF;
    const uint32_t mbar_base = smem_base + SMEM_MBAR_OFF;

    const int tid  = threadIdx.x;
    const int lane = tid & 31;
    const int wid  = tid >> 5;
    const int cta_tok = blockIdx.x * (TOK_PER_STAGE * N_STAGES);

    if (tid == 0) {
        #pragma unroll
        for (int b = 0; b < 3; b++) mbar_init(mbar_base + b * 8, 1);
    }
    __syncthreads();

    // prologue: prefetch stages 0 and 1
    if (tid == 0) {
        #pragma unroll
        for (int s = 0; s < 2; s++) {
            mbar_expect_tx(mbar_base + s * 8, STAGE_BYTES);
            bulk_load(in_base + s * STAGE_BYTES,
                      x + (size_t)(cta_tok + s * TOK_PER_STAGE) * HIDDEN,
                      STAGE_BYTES, mbar_base + s * 8);
        }
    }

    cudaGridDependencySynchronize();   // d_pk ready (overlapped with TMA)

    for (int s = 0; s < N_STAGES; s++) {
        const int bin  = s % 3;
        const int bout = s & 1;
        mbar_wait(mbar_base + bin * 8, (s / 3) & 1);
        __syncthreads();               // all prior-stage smem reads complete

        if (tid == 0) {
            if (s + 2 < N_STAGES) {    // prefetch stage s+2 (buffer just freed)
                const int bn = (s + 2) % 3;
                mbar_expect_tx(mbar_base + bn * 8, STAGE_BYTES);
                bulk_load(in_base + bn * STAGE_BYTES,
                          x + (size_t)(cta_tok + (s + 2) * TOK_PER_STAGE) * HIDDEN,
                          STAGE_BYTES, mbar_base + bn * 8);
            }
            // out buffer bout: store from stage s-2 must have drained
            asm volatile("cp.async.bulk.wait_group.read 1;" ::: "memory");
        }
        __syncthreads();               // out buffer free, data visible

        // ---- compute: warp wid handles token (s*8 + wid) --------------------
        const int token = cta_tok + s * TOK_PER_STAGE + wid;
        int e0, e1; __half2 w0h, w1h;
        route8(__ldg(&logits4[token * 2]), __ldg(&logits4[token * 2 + 1]),
               e0, e1, w0h, w1h);

        const float4* row = (const float4*)(smem + SMEM_IN_OFF +
                                            bin * STAGE_BYTES + wid * (HIDDEN * 4));
        float4* orow = (float4*)(smem + SMEM_OUT_OFF +
                                 bout * STAGE_BYTES + wid * (HIDDEN * 4));

        float4 v[8];
        float sum = 0.0f, sq = 0.0f;
        #pragma unroll
        for (int k = 0; k < 8; k++) {
            v[k] = row[lane + 32 * k];
            sum += v[k].x + v[k].y + v[k].z + v[k].w;
            sq = fmaf(v[k].x, v[k].x, sq); sq = fmaf(v[k].y, v[k].y, sq);
            sq = fmaf(v[k].z, v[k].z, sq); sq = fmaf(v[k].w, v[k].w, sq);
        }
        #pragma unroll
        for (int off = 16; off > 0; off >>= 1) {
            sum += __shfl_xor_sync(0xFFFFFFFFu, sum, off);
            sq  += __shfl_xor_sync(0xFFFFFFFFu, sq,  off);
        }
        const float mean = sum * (1.0f / HIDDEN);
        const float var  = fmaf(-mean, mean, sq * (1.0f / HIDDEN));
        const float rstd = rsqrtf(var + EPS);
        const float mr   = -mean * rstd;

        const __half2* pk0 = d_pk + e0 * HIDDEN;
        const __half2* pk1 = d_pk + e1 * HIDDEN;
        #pragma unroll
        for (int k = 0; k < 8; k++) {
            const int h4 = lane + 32 * k;
            const int h  = 4 * h4;
            const uint4 r0 = *(const uint4*)(pk0 + h);
            const uint4 r1 = *(const uint4*)(pk1 + h);
            __half2 a, b; float2 fb; float4 o;
            a = *(const __half2*)&r0.x; b = *(const __half2*)&r1.x;
            fb = __half22float2(__hfma2(a, w0h, __hmul2(b, w1h)));
            o.x = fmaf(fmaf(v[k].x, rstd, mr), fb.x, fb.y);
            a = *(const __half2*)&r0.y; b = *(const __half2*)&r1.y;
            fb = __half22float2(__hfma2(a, w0h, __hmul2(b, w1h)));
            o.y = fmaf(fmaf(v[k].y, rstd, mr), fb.x, fb.y);
            a = *(const __half2*)&r0.z; b = *(const __half2*)&r1.z;
            fb = __half22float2(__hfma2(a, w0h, __hmul2(b, w1h)));
            o.z = fmaf(fmaf(v[k].z, rstd, mr), fb.x, fb.y);
            a = *(const __half2*)&r0.w; b = *(const __half2*)&r1.w;
            fb = __half22float2(__hfma2(a, w0h, __hmul2(b, w1h)));
            o.w = fmaf(fmaf(v[k].w, rstd, mr), fb.x, fb.y);
            orow[h4] = o;
        }
        __syncthreads();               // all STS for this stage complete

        if (tid == 0) {
            asm volatile("fence.proxy.async.shared::cta;" ::: "memory");
            bulk_store(out + (size_t)(cta_tok + s * TOK_PER_STAGE) * HIDDEN,
                       out_base + bout * STAGE_BYTES, STAGE_BYTES);
            asm volatile("cp.async.bulk.commit_group;" ::: "memory");
        }
    }
    if (tid == 0)
        asm volatile("cp.async.bulk.wait_group 0;" ::: "memory");
}

// ------------------------------------------------------------------ launch
extern "C" void kernel_launch(void* const* d_in, const int* in_sizes, int n_in,
                              void* d_out, int out_size) {
    const float*  x       = (const float*)d_in[0];   // hidden_states [N, H]
    const float4* logits4 = (const float4*)d_in[1];  // router_logits [N, 8]
    const float4* gamma4  = (const float4*)d_in[2];  // [E, H]
    const float4* beta4   = (const float4*)d_in[3];  // [E, H]
    float* out            = (float*)d_out;

    k_pack<<<8, 256>>>(gamma4, beta4);

    static int smem_set = 0;
    if (!smem_set) {
        cudaFuncSetAttribute(smile_moe_norm_kernel,
                             cudaFuncAttributeMaxDynamicSharedMemorySize, SMEM_TOTAL);
        smem_set = 1;
    }

    cudaLaunchConfig_t cfg = {};
    cfg.gridDim  = dim3(GRID, 1, 1);
    cfg.blockDim = dim3(256, 1, 1);
    cfg.dynamicSmemBytes = SMEM_TOTAL;
    cudaLaunchAttribute attr[1];
    attr[0].id = cudaLaunchAttributeProgrammaticStreamSerialization;
    attr[0].val.programmaticStreamSerializationAllowed = 1;
    cfg.attrs = attr;
    cfg.numAttrs = 1;
    cudaLaunchKernelEx(&cfg, smile_moe_norm_kernel, x, logits4, out);
}

// round 12
// speedup vs baseline: 1.5190x; 1.5190x over previous
#include <cuda_runtime.h>
#include <cuda_fp16.h>

// SmileMoENorm — FINAL: exact R6 configuration (measured best: 159.0 us).
//
// Eleven rounds established this is the LTS-cap floor:
//  - Mandatory L2/DRAM traffic: 1.028 GB (x read + f32 out write); the
//    fp16-packed (gamma,beta) table minimized ancillary bytes (R4: -13%).
//  - Main kernel runs at 6617 GB/s ~= the ~6300 B/cyc full-chip LTS cap
//    (path-independent; confirmed by R11's TMA experiment landing at 54%).
//  - Perturbations all regressed: +occupancy (R5/R8), 256-bit LDG/STG (R7),
//    per-warp 2-token pipeline (R10), global pair-sort (R2), smem staging
//    (R3), TMA bulk staging (R11).
// Structure: one warp per token; full row single-read into v[8] (.cs);
// top-2 routing computed in-warp (softmax denominator cancels -> sigmoid);
// fp16-packed affine table built by k_pack, overlapped via PDL; .cs stores.

#define N_TOKENS    131072
#define HIDDEN      1024
#define NUM_EXPERTS 8
#define H4          (HIDDEN / 4)
#define EPS         1e-5f

__device__ __half2 d_pk[NUM_EXPERTS * HIDDEN];   // (gamma, beta) per element

// ---- pre-pass: pack gamma/beta into fp16 ----------------------------------
__global__ void k_pack(const float* __restrict__ gamma,
                       const float* __restrict__ beta) {
    const int i = blockIdx.x * blockDim.x + threadIdx.x;   // 0..8191
    d_pk[i] = __floats2half2_rn(gamma[i], beta[i]);
}

// ------------------------------------------------------------- main kernel
__global__ __launch_bounds__(256, 4)
void smile_moe_norm_kernel(const float4* __restrict__ x,
                           const float4* __restrict__ logits4,   // [N,2] float4
                           float4* __restrict__ out) {
    const int warp_in_block = threadIdx.x >> 5;
    const int lane          = threadIdx.x & 31;
    const int token         = blockIdx.x * (blockDim.x >> 5) + warp_in_block;

    // ---- router: top-2 of 8 logits, renormalized softmax weights ----------
    const float4 la = __ldg(&logits4[token * 2 + 0]);
    const float4 lb = __ldg(&logits4[token * 2 + 1]);
    float l[NUM_EXPERTS] = { la.x, la.y, la.z, la.w, lb.x, lb.y, lb.z, lb.w };

    float best = l[0], second = -3.4e38f;
    int   e0 = 0,     e1 = 0;
    #pragma unroll
    for (int i = 1; i < NUM_EXPERTS; i++) {
        float v = l[i];
        if (v > best)        { second = best; e1 = e0; best = v; e0 = i; }
        else if (v > second) { second = v; e1 = i; }
    }
    const float t  = __expf(second - best);     // full-softmax denom cancels
    const float w0 = 1.0f / (1.0f + t);
    const float w1 = 1.0f - w0;
    const __half2 w0h = __float2half2_rn(w0);
    const __half2 w1h = __float2half2_rn(w1);

    // ---- pass over row: registers + warp reduction (streaming loads) -------
    const float4* xr = x + (size_t)token * H4;
    float4 v[8];
    float sum = 0.0f, sq = 0.0f;
    #pragma unroll
    for (int k = 0; k < 8; k++) {
        v[k] = __ldcs(&xr[lane + 32 * k]);      // touch-once: evict-first
        sum += v[k].x + v[k].y + v[k].z + v[k].w;
        sq = fmaf(v[k].x, v[k].x, sq); sq = fmaf(v[k].y, v[k].y, sq);
        sq = fmaf(v[k].z, v[k].z, sq); sq = fmaf(v[k].w, v[k].w, sq);
    }
    #pragma unroll
    for (int off = 16; off > 0; off >>= 1) {
        sum += __shfl_xor_sync(0xFFFFFFFFu, sum, off);
        sq  += __shfl_xor_sync(0xFFFFFFFFu, sq,  off);
    }
    const float mean = sum * (1.0f / HIDDEN);
    const float var  = fmaf(-mean, mean, sq * (1.0f / HIDDEN));
    const float rstd = rsqrtf(var + EPS);
    const float mr   = -mean * rstd;            // normed = x*rstd + mr

    // PDL: d_pk is written by k_pack; wait for it only now (hidden latency).
    cudaGridDependencySynchronize();

    // ---- epilogue: packed-fp16 blended affine + streaming store -------------
    const __half2* pk0 = d_pk + e0 * HIDDEN;
    const __half2* pk1 = d_pk + e1 * HIDDEN;
    float4* orow = out + (size_t)token * H4;

    #pragma unroll
    for (int k = 0; k < 8; k++) {
        const int h4 = lane + 32 * k;           // float4 index
        const int h  = 4 * h4;                  // element index
        const uint4 r0 = *(const uint4*)(pk0 + h);
        const uint4 r1 = *(const uint4*)(pk1 + h);

        const float nx = fmaf(v[k].x, rstd, mr);
        const float ny = fmaf(v[k].y, rstd, mr);
        const float nz = fmaf(v[k].z, rstd, mr);
        const float nw = fmaf(v[k].w, rstd, mr);

        __half2 a, b; float2 fb; float4 o;
        a = *(const __half2*)&r0.x; b = *(const __half2*)&r1.x;
        fb = __half22float2(__hfma2(a, w0h, __hmul2(b, w1h)));
        o.x = fmaf(nx, fb.x, fb.y);

        a = *(const __half2*)&r0.y; b = *(const __half2*)&r1.y;
        fb = __half22float2(__hfma2(a, w0h, __hmul2(b, w1h)));
        o.y = fmaf(ny, fb.x, fb.y);

        a = *(const __half2*)&r0.z; b = *(const __half2*)&r1.z;
        fb = __half22float2(__hfma2(a, w0h, __hmul2(b, w1h)));
        o.z = fmaf(nz, fb.x, fb.y);

        a = *(const __half2*)&r0.w; b = *(const __half2*)&r1.w;
        fb = __half22float2(__hfma2(a, w0h, __hmul2(b, w1h)));
        o.w = fmaf(nw, fb.x, fb.y);

        __stcs(&orow[h4], o);                   // streaming store
    }
}

// ------------------------------------------------------------------ launch
extern "C" void kernel_launch(void* const* d_in, const int* in_sizes, int n_in,
                              void* d_out, int out_size) {
    const float4* x       = (const float4*)d_in[0];  // hidden_states [N, H]
    const float4* logits4 = (const float4*)d_in[1];  // router_logits [N, 8]
    const float*  gamma   = (const float*)d_in[2];   // [E, H]
    const float*  beta    = (const float*)d_in[3];   // [E, H]
    float4* out           = (float4*)d_out;

    k_pack<<<(NUM_EXPERTS * HIDDEN) / 256, 256>>>(gamma, beta);

    // Main kernel with programmatic dependent launch: overlaps with k_pack;
    // the in-kernel cudaGridDependencySynchronize() provides the ordering.
    cudaLaunchConfig_t cfg = {};
    cfg.gridDim  = dim3(N_TOKENS / 8, 1, 1);         // 8 warps/block
    cfg.blockDim = dim3(256, 1, 1);
    cudaLaunchAttribute attr[1];
    attr[0].id = cudaLaunchAttributeProgrammaticStreamSerialization;
    attr[0].val.programmaticStreamSerializationAllowed = 1;
    cfg.attrs = attr;
    cfg.numAttrs = 1;
    cudaLaunchKernelEx(&cfg, smile_moe_norm_kernel, x, logits4, out);
}